// round 13
// baseline (speedup 1.0000x reference)
#include <cuda_runtime.h>
#include <cstdint>

#define MBLK    64
#define PDIM    256
#define ROWLEN  16384
#define KTOT    768
#define BK      32
#define NT      24          // K tiles
#define STAGES  3
#define STAGE_BYTES 32768   // A 16KB + B 16KB, 32B-granule swizzle
#define SMEM_BYTES  (STAGES * STAGE_BYTES)   // 98304 -> 2 CTAs/SM

// repacked weights [i][q][768] K-contig, tf32-rounded,
// pre-scaled by (1+2^-11) to compensate raw-A tf32 truncation
__device__ float g_w[(size_t)MBLK * PDIM * KTOT];

// ---------- weight repack ----------
__global__ void cvt_w_kernel(const float* __restrict__ Wd,
                             const float* __restrict__ Wu,
                             const float* __restrict__ Wl,
                             const float* __restrict__ Wtr,
                             const float* __restrict__ Wbl) {
    size_t idx = (size_t)blockIdx.x * blockDim.x + threadIdx.x;
    size_t total = (size_t)MBLK * PDIM * KTOT;
    if (idx >= total) return;
    int i = (int)(idx / ((size_t)PDIM * KTOT));
    int r = (int)(idx % ((size_t)PDIM * KTOT));
    int q = r / KTOT;
    int k = r % KTOT;
    int seg = k >> 8;
    int p = k & 255;
    float v;
    if (seg == 0) {
        v = (i == 0) ? Wtr[q * PDIM + p]
                     : Wl[(size_t)(i - 1) * PDIM * PDIM + q * PDIM + p];
    } else if (seg == 1) {
        v = Wd[(size_t)i * PDIM * PDIM + q * PDIM + p];
    } else {
        v = (i == MBLK - 1) ? Wbl[q * PDIM + p]
                            : Wu[(size_t)i * PDIM * PDIM + q * PDIM + p];
    }
    v *= 1.00048828125f;   // 1 + 2^-11
    uint32_t u;
    asm("cvt.rna.tf32.f32 %0, %1;" : "=r"(u) : "f"(v));
    g_w[idx] = __uint_as_float(u);
}

// ---------- tf32 legacy-HMMA GEMM ----------
// Grid (32 mb, 2 nb, 64 i), 128 threads, CTA tile 128x128x32,
// 4 warps 2x2 (64x64), 3-stage cp.async ring, 2 CTAs/SM.
// A raw fp32 (HW truncation, compensated in W). Virtual-k relabel
// (lane tg -> physical k pair (2tg, 2tg+1)) on BOTH operands makes every
// fragment read an LDS.64; 32B-granule swizzle keeps them conflict-free.
__global__ void __launch_bounds__(128, 2)
bxd_gemm(const float* __restrict__ x, float* __restrict__ out) {
    extern __shared__ char smem[];
    uint32_t sbase;
    asm("{ .reg .u64 t; cvta.to.shared.u64 t, %1; cvt.u32.u64 %0, t; }"
        : "=r"(sbase) : "l"(smem));

    const int tid = threadIdx.x;
    const int mb = blockIdx.x;   // batch tile 0..31
    const int nb = blockIdx.y;   // n tile 0..1
    const int i  = blockIdx.z;   // block row 0..63

    const int warp = tid >> 5, lane = tid & 31;
    const int wr = warp >> 1, wc = warp & 1;
    const int g  = lane >> 2, tg = lane & 3;

    int jcol[3];
    jcol[0] = (i + MBLK - 1) & (MBLK - 1);
    jcol[1] = i;
    jcol[2] = (i + 1) & (MBLK - 1);

    // ---- cp.async lanes: lrow 0..15 (+16t), lk4 = 16B chunk 0..7
    const int lrow = tid >> 3;
    const int lk4  = tid & 7;
    // 32B-granule swizzle: granule (lk4>>1) ^ (row&3), 16B half lk4&1
    const int chk  = ((((lk4 >> 1) ^ (lrow & 3)) << 5) | ((lk4 & 1) << 4));
    const float* gA = x + (size_t)(mb * 128 + lrow) * ROWLEN + lk4 * 4;
    const float* gB = g_w + (size_t)(i * 256 + nb * 128 + lrow) * KTOT + lk4 * 4;
    const uint32_t sA = sbase + lrow * 128 + chk;
    const uint32_t sB = sA + 16384;

    // ---- fragment base byte offsets (within stage), LDS.64 layout:
    // addr = row*128 + ((ks ^ (g&3))<<5) + tg*8
    uint32_t aRow[4][2], bRow[8];
#pragma unroll
    for (int mf = 0; mf < 4; mf++) {
        aRow[mf][0] = (wr * 64 + mf * 16 + g) * 128 + tg * 8;
        aRow[mf][1] = aRow[mf][0] + 8 * 128;
    }
#pragma unroll
    for (int nf = 0; nf < 8; nf++)
        bRow[nf] = 16384 + (wc * 64 + nf * 8 + g) * 128 + tg * 8;

    float acc[4][8][4];
#pragma unroll
    for (int mf = 0; mf < 4; mf++)
#pragma unroll
        for (int nf = 0; nf < 8; nf++)
#pragma unroll
            for (int c = 0; c < 4; c++) acc[mf][nf][c] = 0.0f;

    uint32_t a[2][4][4], b[2][8][2];

    auto issue_A = [&](int kt) {
        const uint32_t st = (kt % STAGES) * STAGE_BYTES;
        const float* a0 = gA + jcol[kt >> 3] * PDIM + (kt & 7) * BK;
#pragma unroll
        for (int t = 0; t < 8; t++)
            asm volatile("cp.async.cg.shared.global [%0], [%1], 16;"
                         :: "r"(sA + st + t * 16 * 128),
                            "l"(a0 + (size_t)t * 16 * ROWLEN));
    };
    auto issue_B = [&](int kt) {
        const uint32_t st = (kt % STAGES) * STAGE_BYTES;
        const float* b0 = gB + kt * BK;
#pragma unroll
        for (int t = 0; t < 8; t++)
            asm volatile("cp.async.cg.shared.global [%0], [%1], 16;"
                         :: "r"(sB + st + t * 16 * 128),
                            "l"(b0 + (size_t)t * 16 * KTOT));
    };

    auto load_frags = [&](uint32_t st, int ks, int buf) {
        const uint32_t gsw = ((uint32_t)(ks ^ (g & 3)) << 5);
        // A: two LDS.64 per mf -> (a0,a2) row, (a1,a3) row+8 (virtual-k pairs)
#pragma unroll
        for (int mf = 0; mf < 4; mf++) {
            asm volatile("ld.shared.v2.b32 {%0, %1}, [%2];"
                         : "=r"(a[buf][mf][0]), "=r"(a[buf][mf][2])
                         : "r"(st + aRow[mf][0] + gsw));
            asm volatile("ld.shared.v2.b32 {%0, %1}, [%2];"
                         : "=r"(a[buf][mf][1]), "=r"(a[buf][mf][3])
                         : "r"(st + aRow[mf][1] + gsw));
        }
        // B: one LDS.64 per nf -> (b0,b1)
#pragma unroll
        for (int nf = 0; nf < 8; nf++)
            asm volatile("ld.shared.v2.b32 {%0, %1}, [%2];"
                         : "=r"(b[buf][nf][0]), "=r"(b[buf][nf][1])
                         : "r"(st + bRow[nf] + gsw));
    };

    issue_A(0); issue_B(0);
    asm volatile("cp.async.commit_group;");
    issue_A(1); issue_B(1);
    asm volatile("cp.async.commit_group;");

    for (int kt = 0; kt < NT; kt++) {
        asm volatile("cp.async.wait_group 1;");
        __syncthreads();

        const uint32_t st = sbase + (kt % STAGES) * STAGE_BYTES;
        const bool pre = (kt + 2 < NT);

        load_frags(st, 0, 0);
#pragma unroll
        for (int ks = 0; ks < 4; ks++) {
            // interleave next-tile global loads under tensor-busy windows
            if (ks == 1 && pre) issue_A(kt + 2);
            if (ks == 2 && pre) issue_B(kt + 2);
            if (ks < 3) load_frags(st, ks + 1, (ks + 1) & 1);
            const int cur = ks & 1;
#pragma unroll
            for (int mf = 0; mf < 4; mf++)
#pragma unroll
                for (int nf = 0; nf < 8; nf++) {
                    float* c = acc[mf][nf];
                    asm volatile(
                        "mma.sync.aligned.m16n8k8.row.col.f32.tf32.tf32.f32 "
                        "{%0,%1,%2,%3}, {%4,%5,%6,%7}, {%8,%9}, {%0,%1,%2,%3};\n"
                        : "+f"(c[0]), "+f"(c[1]), "+f"(c[2]), "+f"(c[3])
                        : "r"(a[cur][mf][0]), "r"(a[cur][mf][1]),
                          "r"(a[cur][mf][2]), "r"(a[cur][mf][3]),
                          "r"(b[cur][nf][0]), "r"(b[cur][nf][1]));
                }
        }
        asm volatile("cp.async.commit_group;");
    }

    // epilogue: direct float2 stores (fragment layout (g, 2tg))
    size_t obase = (size_t)(mb * 128 + wr * 64) * ROWLEN
                 + (size_t)i * PDIM + nb * 128 + wc * 64;
#pragma unroll
    for (int mf = 0; mf < 4; mf++) {
#pragma unroll
        for (int nf = 0; nf < 8; nf++) {
            int row = mf * 16 + g;
            int col = nf * 8 + tg * 2;
            float2 v0 = make_float2(acc[mf][nf][0], acc[mf][nf][1]);
            float2 v1 = make_float2(acc[mf][nf][2], acc[mf][nf][3]);
            *reinterpret_cast<float2*>(out + obase + (size_t)row * ROWLEN + col) = v0;
            *reinterpret_cast<float2*>(out + obase + (size_t)(row + 8) * ROWLEN + col) = v1;
        }
    }
}

// ---------------- launcher ----------------
extern "C" void kernel_launch(void* const* d_in, const int* in_sizes, int n_in,
                              void* d_out, int out_size) {
    const float* x   = (const float*)d_in[0];
    const float* Wd  = (const float*)d_in[1];
    const float* Wu  = (const float*)d_in[2];
    const float* Wl  = (const float*)d_in[3];
    const float* Wtr = (const float*)d_in[4];
    const float* Wbl = (const float*)d_in[5];
    float* out = (float*)d_out;

    cvt_w_kernel<<<49152, 256>>>(Wd, Wu, Wl, Wtr, Wbl);

    (void)cudaFuncSetAttribute(bxd_gemm,
                               cudaFuncAttributeMaxDynamicSharedMemorySize,
                               SMEM_BYTES);
    bxd_gemm<<<dim3(32, 2, 64), 128, SMEM_BYTES>>>(x, out);
}

// round 14
// speedup vs baseline: 1.2013x; 1.2013x over previous
#include <cuda_runtime.h>
#include <cstdint>

#define MBLK    64
#define PDIM    256
#define ROWLEN  16384
#define KTOT    768
#define BK      32
#define NT      24          // K tiles
#define STAGES  3
#define STAGE_BYTES 32768   // A 16KB + B 16KB, swizzled
#define SMEM_BYTES  (STAGES * STAGE_BYTES)   // 98304 -> 2 CTAs/SM

// repacked weights [i][q][768], tf32-rounded, truncation-compensated,
// k-permuted within 8-groups as [0,4,1,5,2,6,3,7] for LDS.64 fragments
__device__ float g_w[(size_t)MBLK * PDIM * KTOT];

// ---------- weight repack (vectorized: one 8-float group per thread) ----------
// out group kp[0..7] <- k {0,4,1,5,2,6,3,7}: load lo=src[k0..3], hi=src[k4..7],
// out0={lo.x,hi.x,lo.y,hi.y}, out1={lo.z,hi.z,lo.w,hi.w}
__global__ void cvt_w_kernel(const float* __restrict__ Wd,
                             const float* __restrict__ Wu,
                             const float* __restrict__ Wl,
                             const float* __restrict__ Wtr,
                             const float* __restrict__ Wbl) {
    const int gidx = blockIdx.x * blockDim.x + threadIdx.x;   // 8-float group
    const int GPI = PDIM * KTOT / 8;                           // 24576 groups per i
    if (gidx >= MBLK * GPI) return;
    const int i  = gidx / GPI;
    const int r  = gidx - i * GPI;
    const int q  = r / 96;          // 96 groups per output row
    const int kg = r - q * 96;      // group within row
    const int seg = kg >> 5;        // /32
    const int p8  = (kg & 31) << 3; // p base within 256

    const float* src;
    if (seg == 0) {
        src = (i == 0) ? Wtr : Wl + (size_t)(i - 1) * PDIM * PDIM;
    } else if (seg == 1) {
        src = Wd + (size_t)i * PDIM * PDIM;
    } else {
        src = (i == MBLK - 1) ? Wbl : Wu + (size_t)i * PDIM * PDIM;
    }
    src += (size_t)q * PDIM + p8;

    float4 lo = *reinterpret_cast<const float4*>(src);
    float4 hi = *reinterpret_cast<const float4*>(src + 4);

    const float comp = 1.00048828125f;   // 1 + 2^-11 (raw-A truncation comp)
    float v[8] = { lo.x, hi.x, lo.y, hi.y, lo.z, hi.z, lo.w, hi.w };
    uint32_t u[8];
#pragma unroll
    for (int j = 0; j < 8; j++) {
        float t = v[j] * comp;
        asm("cvt.rna.tf32.f32 %0, %1;" : "=r"(u[j]) : "f"(t));
    }
    float4* dst = reinterpret_cast<float4*>(g_w + (size_t)gidx * 8);
    dst[0] = make_float4(__uint_as_float(u[0]), __uint_as_float(u[1]),
                         __uint_as_float(u[2]), __uint_as_float(u[3]));
    dst[1] = make_float4(__uint_as_float(u[4]), __uint_as_float(u[5]),
                         __uint_as_float(u[6]), __uint_as_float(u[7]));
}

// ---------- tf32 legacy-HMMA GEMM (R10 champion, unchanged) ----------
// Grid (32 mb, 2 nb, 64 i), 128 threads, CTA tile 128x128x32,
// 4 warps 2x2 (64x64), 3-stage cp.async ring, XOR swizzle, 2 CTAs/SM.
// A fed raw (HW tf32-truncation, compensated in W); B frags via LDS.64.
__global__ void __launch_bounds__(128, 2)
bxd_gemm(const float* __restrict__ x, float* __restrict__ out) {
    extern __shared__ char smem[];
    uint32_t sbase;
    asm("{ .reg .u64 t; cvta.to.shared.u64 t, %1; cvt.u32.u64 %0, t; }"
        : "=r"(sbase) : "l"(smem));

    const int tid = threadIdx.x;
    const int mb = blockIdx.x;   // batch tile 0..31
    const int nb = blockIdx.y;   // n tile 0..1
    const int i  = blockIdx.z;   // block row 0..63

    const int warp = tid >> 5, lane = tid & 31;
    const int wr = warp >> 1, wc = warp & 1;
    const int g  = lane >> 2, tg = lane & 3;

    int jcol[3];
    jcol[0] = (i + MBLK - 1) & (MBLK - 1);
    jcol[1] = i;
    jcol[2] = (i + 1) & (MBLK - 1);

    // ---- cp.async lanes
    const int lrow = tid >> 3;
    const int lk4  = tid & 7;
    const int chk  = ((lk4 ^ (lrow & 7)) << 4);
    const float* gA = x + (size_t)(mb * 128 + lrow) * ROWLEN + lk4 * 4;
    const float* gB = g_w + (size_t)(i * 256 + nb * 128 + lrow) * KTOT + lk4 * 4;
    const uint32_t sA = sbase + lrow * 128 + chk;
    const uint32_t sB = sA + 16384;

    // ---- fragment read byte offsets (within stage)
    uint32_t aRow[4][2], bRow[8];
#pragma unroll
    for (int mf = 0; mf < 4; mf++) {
        aRow[mf][0] = (wr * 64 + mf * 16 + g) * 128 + tg * 4;
        aRow[mf][1] = aRow[mf][0] + 8 * 128;
    }
    // B: LDS.64 base; chunk selected per ks: ((2ks + (tg>>1)) ^ g) * 16 + (tg&1)*8
#pragma unroll
    for (int nf = 0; nf < 8; nf++)
        bRow[nf] = 16384 + (wc * 64 + nf * 8 + g) * 128 + (tg & 1) * 8;

    float acc[4][8][4];
#pragma unroll
    for (int mf = 0; mf < 4; mf++)
#pragma unroll
        for (int nf = 0; nf < 8; nf++)
#pragma unroll
            for (int c = 0; c < 4; c++) acc[mf][nf][c] = 0.0f;

    uint32_t a[2][4][4], b[2][8][2];

    auto issue_A = [&](int kt) {
        const uint32_t st = (kt % STAGES) * STAGE_BYTES;
        const float* a0 = gA + jcol[kt >> 3] * PDIM + (kt & 7) * BK;
#pragma unroll
        for (int t = 0; t < 8; t++)
            asm volatile("cp.async.cg.shared.global [%0], [%1], 16;"
                         :: "r"(sA + st + t * 16 * 128),
                            "l"(a0 + (size_t)t * 16 * ROWLEN));
    };
    auto issue_B = [&](int kt) {
        const uint32_t st = (kt % STAGES) * STAGE_BYTES;
        const float* b0 = gB + kt * BK;
#pragma unroll
        for (int t = 0; t < 8; t++)
            asm volatile("cp.async.cg.shared.global [%0], [%1], 16;"
                         :: "r"(sB + st + t * 16 * 128),
                            "l"(b0 + (size_t)t * 16 * KTOT));
    };

    auto load_frags = [&](uint32_t st, int ks, int buf) {
        const uint32_t c0 = (((2 * ks) ^ g) << 4);
        const uint32_t c1 = (((2 * ks + 1) ^ g) << 4);
        // A: raw fp32 bits (HW truncates to tf32; compensated in W)
#pragma unroll
        for (int mf = 0; mf < 4; mf++) {
            asm volatile("ld.shared.b32 %0, [%1];" : "=r"(a[buf][mf][0]) : "r"(st + aRow[mf][0] + c0));
            asm volatile("ld.shared.b32 %0, [%1];" : "=r"(a[buf][mf][1]) : "r"(st + aRow[mf][1] + c0));
            asm volatile("ld.shared.b32 %0, [%1];" : "=r"(a[buf][mf][2]) : "r"(st + aRow[mf][0] + c1));
            asm volatile("ld.shared.b32 %0, [%1];" : "=r"(a[buf][mf][3]) : "r"(st + aRow[mf][1] + c1));
        }
        // B: one LDS.64 per nf (k-permuted layout: {k=tg, k=tg+4} contiguous)
        const uint32_t bc = (((2 * ks + (tg >> 1)) ^ g) << 4);
#pragma unroll
        for (int nf = 0; nf < 8; nf++)
            asm volatile("ld.shared.v2.b32 {%0, %1}, [%2];"
                         : "=r"(b[buf][nf][0]), "=r"(b[buf][nf][1])
                         : "r"(st + bRow[nf] + bc));
    };

    issue_A(0); issue_B(0);
    asm volatile("cp.async.commit_group;");
    issue_A(1); issue_B(1);
    asm volatile("cp.async.commit_group;");

    for (int kt = 0; kt < NT; kt++) {
        asm volatile("cp.async.wait_group 1;");
        __syncthreads();

        const uint32_t st = sbase + (kt % STAGES) * STAGE_BYTES;
        const bool pre = (kt + 2 < NT);

        load_frags(st, 0, 0);
#pragma unroll
        for (int ks = 0; ks < 4; ks++) {
            // interleave next-tile global loads under tensor-busy windows
            if (ks == 1 && pre) issue_A(kt + 2);
            if (ks == 2 && pre) issue_B(kt + 2);
            if (ks < 3) load_frags(st, ks + 1, (ks + 1) & 1);
            const int cur = ks & 1;
#pragma unroll
            for (int mf = 0; mf < 4; mf++)
#pragma unroll
                for (int nf = 0; nf < 8; nf++) {
                    float* c = acc[mf][nf];
                    asm volatile(
                        "mma.sync.aligned.m16n8k8.row.col.f32.tf32.tf32.f32 "
                        "{%0,%1,%2,%3}, {%4,%5,%6,%7}, {%8,%9}, {%0,%1,%2,%3};\n"
                        : "+f"(c[0]), "+f"(c[1]), "+f"(c[2]), "+f"(c[3])
                        : "r"(a[cur][mf][0]), "r"(a[cur][mf][1]),
                          "r"(a[cur][mf][2]), "r"(a[cur][mf][3]),
                          "r"(b[cur][nf][0]), "r"(b[cur][nf][1]));
                }
        }
        asm volatile("cp.async.commit_group;");
    }

    // epilogue: direct float2 stores (fragment layout (g, 2tg))
    size_t obase = (size_t)(mb * 128 + wr * 64) * ROWLEN
                 + (size_t)i * PDIM + nb * 128 + wc * 64;
#pragma unroll
    for (int mf = 0; mf < 4; mf++) {
#pragma unroll
        for (int nf = 0; nf < 8; nf++) {
            int row = mf * 16 + g;
            int col = nf * 8 + tg * 2;
            float2 v0 = make_float2(acc[mf][nf][0], acc[mf][nf][1]);
            float2 v1 = make_float2(acc[mf][nf][2], acc[mf][nf][3]);
            *reinterpret_cast<float2*>(out + obase + (size_t)row * ROWLEN + col) = v0;
            *reinterpret_cast<float2*>(out + obase + (size_t)(row + 8) * ROWLEN + col) = v1;
        }
    }
}

// ---------------- launcher ----------------
extern "C" void kernel_launch(void* const* d_in, const int* in_sizes, int n_in,
                              void* d_out, int out_size) {
    const float* x   = (const float*)d_in[0];
    const float* Wd  = (const float*)d_in[1];
    const float* Wu  = (const float*)d_in[2];
    const float* Wl  = (const float*)d_in[3];
    const float* Wtr = (const float*)d_in[4];
    const float* Wbl = (const float*)d_in[5];
    float* out = (float*)d_out;

    // 64*24576 groups / 256 threads = 6144 blocks
    cvt_w_kernel<<<6144, 256>>>(Wd, Wu, Wl, Wtr, Wbl);

    (void)cudaFuncSetAttribute(bxd_gemm,
                               cudaFuncAttributeMaxDynamicSharedMemorySize,
                               SMEM_BYTES);
    bxd_gemm<<<dim3(32, 2, 64), 128, SMEM_BYTES>>>(x, out);
}